// round 6
// baseline (speedup 1.0000x reference)
#include <cuda_runtime.h>
#include <math.h>

#define NB 4096
#define NK 1024
#define ND 128
#define NQ 4096
#define EPSV 1e-6f
#define SCALE 4294967296.0   // 2^32 fixed-point for deterministic accumulation

typedef unsigned long long u64;
typedef unsigned int u32;

// Scratch (device globals — no allocation allowed in kernel_launch)
__device__ u64   g_skey[ND * NK];       // sorted packed keys, layout [d][i]
__device__ uint4 g_rec[ND * NQ * 2];    // 32B/bucket: kl, k0, k1, (start|end<<16)
__device__ float g_vmin[ND], g_vmax[ND];
__device__ int   g_imin[ND], g_imax[ND];
__device__ u64   g_accum;               // fixed-point loss sum (deterministic)
__device__ u32   g_done;                // finished-block counter

// float -> order-preserving u32 (ascending)
__device__ __forceinline__ u32 enc_f32(float v) {
    u32 b = __float_as_uint(v);
    return (b & 0x80000000u) ? ~b : (b | 0x80000000u);
}
__device__ __forceinline__ float dec_f32(u32 u) {
    u32 b = (u & 0x80000000u) ? (u ^ 0x80000000u) : ~u;
    return __uint_as_float(b);
}

// Exactly monotone bucket map: fp add, mul by +const, float->int trunc are all
// monotone nondecreasing, so v1 <= v2 => bucket(v1) <= bucket(v2), and
// b1 < b2 => v1 < v2 (strict). Equal values map to equal buckets.
__device__ __forceinline__ int bucket_of(float v) {
    float f = (v + 6.0f) * ((float)NQ / 12.0f);
    f = fminf(fmaxf(f, 0.0f), (float)(NQ - 1));
    return (int)f;
}

// ---------------------------------------------------------------------------
// Kernel 1: per-column COUNTING sort of packed (value,index) u64 keys, then
// emit 32B bucket records so the row kernel resolves nearest-neighbor pairs
// with a single 32B load in the common case.
// grid = ND blocks, 512 threads x 2 elements.
// ---------------------------------------------------------------------------
__global__ void __launch_bounds__(512) sort_columns_kernel(const float* __restrict__ cent) {
    __shared__ __align__(16) int s_hist[NQ];       // 16 KB
    __shared__ __align__(16) int s_pref[NQ + 4];   // 16 KB (exclusive prefix)
    __shared__ u64 s_tmp[NK];                      // 8 KB (arrival-order scatter)
    __shared__ u64 s_keys[NK];                     // 8 KB (final sorted)
    __shared__ int s_wsum[16];

    const int d = blockIdx.x;
    const int i = threadIdx.x;
    const int lane = i & 31, w = i >> 5;

    if (d == 0 && i == 0) { g_accum = 0ULL; g_done = 0u; }  // per-launch reset

    const float v0 = cent[i * ND + d];
    const float v1 = cent[(i + 512) * ND + d];
    const u64 k0e = ((u64)enc_f32(v0) << 32) | (u32)i;
    const u64 k1e = ((u64)enc_f32(v1) << 32) | (u32)(i + 512);
    const int b0 = bucket_of(v0), b1 = bucket_of(v1);

    ((int4*)s_hist)[i] = make_int4(0, 0, 0, 0);
    ((int4*)s_hist)[i + 512] = make_int4(0, 0, 0, 0);
    __syncthreads();
    const int r0 = atomicAdd(&s_hist[b0], 1);
    const int r1 = atomicAdd(&s_hist[b1], 1);
    __syncthreads();

    // prefix sum over 4096 bins (8 per thread)
    const int4 ca = ((const int4*)s_hist)[2 * i];
    const int4 cb = ((const int4*)s_hist)[2 * i + 1];
    const int s = ca.x + ca.y + ca.z + ca.w + cb.x + cb.y + cb.z + cb.w;
    int incl = s;
#pragma unroll
    for (int off = 1; off < 32; off <<= 1) {
        int t = __shfl_up_sync(0xffffffffu, incl, off);
        if (lane >= off) incl += t;
    }
    if (lane == 31) s_wsum[w] = incl;
    __syncthreads();
    if (w == 0) {
        int ws = (lane < 16) ? s_wsum[lane] : 0;
#pragma unroll
        for (int off = 1; off < 16; off <<= 1) {
            int t = __shfl_up_sync(0xffffffffu, ws, off);
            if (lane >= off) ws += t;
        }
        if (lane < 16) s_wsum[lane] = ws;
    }
    __syncthreads();
    {
        int p0 = (w > 0 ? s_wsum[w - 1] : 0) + (incl - s);
        int p1 = p0 + ca.x, p2 = p1 + ca.y, p3 = p2 + ca.z, p4 = p3 + ca.w;
        int p5 = p4 + cb.x, p6 = p5 + cb.y, p7 = p6 + cb.z;
        ((int4*)s_pref)[2 * i]     = make_int4(p0, p1, p2, p3);
        ((int4*)s_pref)[2 * i + 1] = make_int4(p4, p5, p6, p7);
    }
    if (i == 0) s_pref[NQ] = NK;
    __syncthreads();

    // scatter in arrival order
    const int st0 = s_pref[b0], st1 = s_pref[b1];
    s_tmp[st0 + r0] = k0e;
    s_tmp[st1 + r1] = k1e;
    __syncthreads();

    // parallel rank placement on unique full keys (deterministic)
    {
        const int cnt0 = s_hist[b0];
        int rank = 0;
        for (int j = 0; j < cnt0; j++) rank += (s_tmp[st0 + j] < k0e);
        s_keys[st0 + rank] = k0e;
        const int cnt1 = s_hist[b1];
        rank = 0;
        for (int j = 0; j < cnt1; j++) rank += (s_tmp[st1 + j] < k1e);
        s_keys[st1 + rank] = k1e;
    }
    __syncthreads();

    // sorted keys (coalesced)
    g_skey[d * NK + i]       = s_keys[i];
    g_skey[d * NK + i + 512] = s_keys[i + 512];

    // bucket records: 8 per thread, warp-contiguous stores
#pragma unroll
    for (int t = 0; t < 8; t++) {
        const int q = i + t * 512;
        const int st = s_pref[q], en = s_pref[q + 1];
        const u64 kl = s_keys[st > 0 ? st - 1 : 0];
        const u64 k0 = s_keys[st < NK ? st : NK - 1];
        const u64 k1 = s_keys[st + 1 < NK ? st + 1 : NK - 1];
        uint4* rp = &g_rec[(d * NQ + q) * 2];
        rp[0] = make_uint4((u32)kl, (u32)(kl >> 32), (u32)k0, (u32)(k0 >> 32));
        rp[1] = make_uint4((u32)k1, (u32)(k1 >> 32), (u32)st | ((u32)en << 16), 0u);
    }

    if (i == 0) {
        // min: first sorted key already has smallest index among min-ties
        g_vmin[d] = dec_f32((u32)(s_keys[0] >> 32));
        g_imin[d] = (int)(s_keys[0] & 1023u);
        // max: first occurrence (smallest idx) = start of the max-value run
        u32 umax = (u32)(s_keys[NK - 1] >> 32);
        int j = NK - 1;
        while (j > 0 && (u32)(s_keys[j - 1] >> 32) == umax) j--;
        g_vmax[d] = dec_f32(umax);
        g_imax[d] = (int)(s_keys[j] & 1023u);
    }
}

// ---------------------------------------------------------------------------
// Nearest-centroid resolve for one (row value, dim): one 32B record load
// resolves ~88% of queries; rare fallback scans the sorted keys.
// ---------------------------------------------------------------------------
__device__ __forceinline__ int resolve_near(const float xv, const int d) {
    const u64 target = ((u64)enc_f32(xv)) << 32;
    const int q = bucket_of(xv);
    const uint4* rp = &g_rec[(d * NQ + q) * 2];
    const uint4 lo = __ldg(rp);
    const uint4 hi = __ldg(rp + 1);
    const u64 kl = (u64)lo.x | ((u64)lo.y << 32);
    const u64 k0 = (u64)lo.z | ((u64)lo.w << 32);
    const u64 k1 = (u64)hi.x | ((u64)hi.y << 32);
    const int st  = (int)(hi.z & 0xffffu);
    const int en  = (int)(hi.z >> 16);
    const int cnt = en - st;

    u64 L, R;
    if (cnt == 0 || target <= k0)      { L = kl; R = k0; }
    else if (cnt == 1 || target <= k1) { L = k0; R = k1; }
    else {
        const int base = d * NK;
        u64 prev = k1, right = 0;
        bool found = false;
        for (int j = st + 2; j < en; j++) {
            u64 cur = __ldg(&g_skey[base + j]);
            if (cur >= target) { right = cur; found = true; break; }
            prev = cur;
        }
        if (!found) right = (en < NK) ? __ldg(&g_skey[base + en]) : prev;
        L = prev; R = right;
    }

    const float vl = dec_f32((u32)(L >> 32));
    const float vr = dec_f32((u32)(R >> 32));
    float sl = xv - vl; sl *= sl;     // compare squares, like reference
    float sr = xv - vr; sr *= sr;
    const int il = (int)(L & 1023u), ir = (int)(R & 1023u);
    return (sl < sr) ? il : (sr < sl) ? ir : min(il, ir);
}

// ---------------------------------------------------------------------------
// Kernel 2: one block per TWO rows, ND threads (thread = dim d, both rows).
// ---------------------------------------------------------------------------
__global__ void __launch_bounds__(ND) row_kernel(const float* __restrict__ x,
                                                 const float* __restrict__ cent,
                                                 float* __restrict__ out) {
    __shared__ u32 hist0[NK], hist1[NK];   // 8 KB, packed (near | far<<16)
    __shared__ u32 s_key[4][4];
    __shared__ float s_sum[6][4];

    const int b0 = blockIdx.x * 2, b1 = b0 + 1;
    const int d = threadIdx.x;
    const int warp = d >> 5, lane = d & 31;

    {
        uint4 z = make_uint4(0, 0, 0, 0);
        ((uint4*)hist0)[d] = z; ((uint4*)hist0)[d + 128] = z;
        ((uint4*)hist1)[d] = z; ((uint4*)hist1)[d + 128] = z;
    }

    const float xv0 = x[b0 * ND + d];
    const float xv1 = x[b1 * ND + d];

    const int n_idx0 = resolve_near(xv0, d);
    const int n_idx1 = resolve_near(xv1, d);

    // ---- farthest: one of the column extremes ----
    const float vmin = g_vmin[d], vmax = g_vmax[d];
    const int   imin = g_imin[d], imax = g_imax[d];
    int f_idx0, f_idx1;
    {
        float sm = xv0 - vmin; sm *= sm;
        float sM = xv0 - vmax; sM *= sM;
        f_idx0 = (sm > sM) ? imin : (sM > sm) ? imax : min(imin, imax);
        sm = xv1 - vmin; sm *= sm;
        sM = xv1 - vmax; sM *= sM;
        f_idx1 = (sm > sM) ? imin : (sM > sm) ? imax : min(imin, imax);
    }

    __syncthreads();  // hist zeroing complete
    u32 cn0 = (atomicAdd(&hist0[n_idx0], 1u) & 0xffffu) + 1u;
    u32 cf0 = (atomicAdd(&hist0[f_idx0], 0x10000u) >> 16) + 1u;
    u32 cn1 = (atomicAdd(&hist1[n_idx1], 1u) & 0xffffu) + 1u;
    u32 cf1 = (atomicAdd(&hist1[f_idx1], 0x10000u) >> 16) + 1u;

    // Running-max mode: last incrementer of each bin sees its final count,
    // so max over thread keys = (max count, smallest bin on ties).
    u32 key0 = (cn0 << 10) | (1023u - (u32)n_idx0);
    u32 key1 = (cf0 << 10) | (1023u - (u32)f_idx0);
    u32 key2 = (cn1 << 10) | (1023u - (u32)n_idx1);
    u32 key3 = (cf1 << 10) | (1023u - (u32)f_idx1);
#pragma unroll
    for (int s = 16; s > 0; s >>= 1) {
        key0 = max(key0, __shfl_xor_sync(0xffffffffu, key0, s));
        key1 = max(key1, __shfl_xor_sync(0xffffffffu, key1, s));
        key2 = max(key2, __shfl_xor_sync(0xffffffffu, key2, s));
        key3 = max(key3, __shfl_xor_sync(0xffffffffu, key3, s));
    }
    if (lane == 0) {
        s_key[0][warp] = key0; s_key[1][warp] = key1;
        s_key[2][warp] = key2; s_key[3][warp] = key3;
    }
    __syncthreads();
    u32 k0 = max(max(s_key[0][0], s_key[0][1]), max(s_key[0][2], s_key[0][3]));
    u32 k1 = max(max(s_key[1][0], s_key[1][1]), max(s_key[1][2], s_key[1][3]));
    u32 k2 = max(max(s_key[2][0], s_key[2][1]), max(s_key[2][2], s_key[2][3]));
    u32 k3 = max(max(s_key[3][0], s_key[3][1]), max(s_key[3][2], s_key[3][3]));
    int mp0 = 1023 - (int)(k0 & 1023u);
    int mn0 = 1023 - (int)(k1 & 1023u);
    int mp1 = 1023 - (int)(k2 & 1023u);
    int mn1 = 1023 - (int)(k3 & 1023u);

    // ---- triplet margin loss (swap=True), eps added per element ----
    float pv0 = __ldg(&cent[mp0 * ND + d]);
    float nv0 = __ldg(&cent[mn0 * ND + d]);
    float pv1 = __ldg(&cent[mp1 * ND + d]);
    float nv1 = __ldg(&cent[mn1 * ND + d]);
    float a0 = xv0 - pv0 + EPSV, b0f = xv0 - nv0 + EPSV, c0f = pv0 - nv0 + EPSV;
    float a1 = xv1 - pv1 + EPSV, b1f = xv1 - nv1 + EPSV, c1f = pv1 - nv1 + EPSV;
    float u0 = a0 * a0, u1 = b0f * b0f, u2 = c0f * c0f;
    float u3 = a1 * a1, u4 = b1f * b1f, u5 = c1f * c1f;
#pragma unroll
    for (int s = 16; s > 0; s >>= 1) {
        u0 += __shfl_xor_sync(0xffffffffu, u0, s);
        u1 += __shfl_xor_sync(0xffffffffu, u1, s);
        u2 += __shfl_xor_sync(0xffffffffu, u2, s);
        u3 += __shfl_xor_sync(0xffffffffu, u3, s);
        u4 += __shfl_xor_sync(0xffffffffu, u4, s);
        u5 += __shfl_xor_sync(0xffffffffu, u5, s);
    }
    if (lane == 0) {
        s_sum[0][warp] = u0; s_sum[1][warp] = u1; s_sum[2][warp] = u2;
        s_sum[3][warp] = u3; s_sum[4][warp] = u4; s_sum[5][warp] = u5;
    }
    __syncthreads();
    if (d == 0) {
        float r[6];
#pragma unroll
        for (int t = 0; t < 6; t++)
            r[t] = s_sum[t][0] + s_sum[t][1] + s_sum[t][2] + s_sum[t][3];
        float dp0 = sqrtf(r[0]);
        float dn0 = fminf(sqrtf(r[1]), sqrtf(r[2]));
        float loss0 = fmaxf(dp0 - dn0 + 1.0f, 0.0f);
        float dp1 = sqrtf(r[3]);
        float dn1 = fminf(sqrtf(r[4]), sqrtf(r[5]));
        float loss1 = fmaxf(dp1 - dn1 + 1.0f, 0.0f);

        // deterministic fixed-point accumulation (integer adds are associative)
        u64 fx = (u64)__double2ll_rn((double)loss0 * SCALE)
               + (u64)__double2ll_rn((double)loss1 * SCALE);
        atomicAdd(&g_accum, fx);
        __threadfence();
        if (atomicAdd(&g_done, 1u) == gridDim.x - 1) {
            u64 acc = atomicAdd(&g_accum, 0ULL);
            out[0] = (float)((double)acc * (1.0 / (4096.0 * SCALE)));
        }
    }
}

extern "C" void kernel_launch(void* const* d_in, const int* in_sizes, int n_in,
                              void* d_out, int out_size) {
    const float* input_features = (const float*)d_in[0];  // [4096, 128]
    const float* centroids      = (const float*)d_in[1];  // [1024, 128]
    float* out = (float*)d_out;

    sort_columns_kernel<<<ND, 512>>>(centroids);
    row_kernel<<<NB / 2, ND>>>(input_features, centroids, out);
}